// round 2
// baseline (speedup 1.0000x reference)
#include <cuda_runtime.h>

// Shapes (fixed): B=8, H=8, N=2048, C=64  -> BH=64 head-batches
#define NTOK 2048
#define CDIM 64
#define NBH  64

// Scratch (alloc-free rule: __device__ globals). 3 x 33.5 MB.
__device__ float g_q[NBH * NTOK * CDIM];
__device__ float g_k[NBH * NTOK * CDIM];
__device__ float g_v[NBH * NTOK * CDIM];

typedef unsigned long long u64;
typedef ulonglong2 ull2;

__device__ __forceinline__ u64 pk2(float lo, float hi) {
    u64 r; asm("mov.b64 %0,{%1,%2};" : "=l"(r) : "f"(lo), "f"(hi)); return r;
}
__device__ __forceinline__ void up2(u64 v, float &lo, float &hi) {
    asm("mov.b64 {%0,%1},%2;" : "=f"(lo), "=f"(hi) : "l"(v));
}
__device__ __forceinline__ u64 f2fma(u64 a, u64 b, u64 c) {
    u64 d; asm("fma.rn.f32x2 %0,%1,%2,%3;" : "=l"(d) : "l"(a), "l"(b), "l"(c)); return d;
}
__device__ __forceinline__ u64 f2mul(u64 a, u64 b) {
    u64 d; asm("mul.rn.f32x2 %0,%1,%2;" : "=l"(d) : "l"(a), "l"(b)); return d;
}

// ---------------------------------------------------------------------------
// Kernel 1: fused QKV projection (unchanged from R1 — small vs attention).
// ---------------------------------------------------------------------------
__global__ void __launch_bounds__(256) qkv_kernel(const float* __restrict__ x,
                                                  const float* __restrict__ W) {
    extern __shared__ float Ws[];  // 192*64 floats = 49152 B
    for (int i = threadIdx.x; i < 192 * 64; i += 256) Ws[i] = W[i];
    __syncthreads();

    int row = blockIdx.x * 256 + threadIdx.x;  // 0 .. 131071
    float xr[64];
    const float4* xp = (const float4*)(x + (size_t)row * 64);
#pragma unroll
    for (int c4 = 0; c4 < 16; c4++) {
        float4 t = xp[c4];
        xr[c4 * 4 + 0] = t.x; xr[c4 * 4 + 1] = t.y;
        xr[c4 * 4 + 2] = t.z; xr[c4 * 4 + 3] = t.w;
    }

    for (int d = 0; d < 192; d += 4) {
        float a0 = 0.f, a1 = 0.f, a2 = 0.f, a3 = 0.f;
        const float* w0 = &Ws[d * 64];
#pragma unroll
        for (int c = 0; c < 64; c++) {
            float xv = xr[c];
            a0 = fmaf(xv, w0[c],        a0);
            a1 = fmaf(xv, w0[64 + c],   a1);
            a2 = fmaf(xv, w0[128 + c],  a2);
            a3 = fmaf(xv, w0[192 + c],  a3);
        }
        float* dst = (d < 64) ? g_q : ((d < 128) ? g_k : g_v);
        int dd = d & 63;
        *(float4*)&dst[(size_t)row * 64 + dd] = make_float4(a0, a1, a2, a3);
    }
}

// ---------------------------------------------------------------------------
// Kernel 2: flash attention, BM=BN=128, 512 threads.
// S microtile 4x8 (col-packed FFMA2), PV microtile 4x4.
// Q/K/P stored c-major with XOR swizzle: addr = c*132 + ((r4 ^ ((c>>2)&7))<<2) + (r&3)
//  -> GEMM-phase reads are broadcasts (conflict-free), transposed writes spread banks.
// ---------------------------------------------------------------------------
#define BM 128
#define BN 128
#define TSTRIDE 132
#define QT_OFF 0
#define KT_OFF (64 * TSTRIDE)                    // 8448
#define VS_OFF (KT_OFF + 64 * TSTRIDE)           // 16896  (Vs: [128][68] row-major)
#define PT_OFF (VS_OFF + 128 * 68)               // 25600
#define SMEM_FLOATS (PT_OFF + 128 * TSTRIDE)     // 42496
#define SMEM_BYTES  (SMEM_FLOATS * 4)            // 169984

__global__ void __launch_bounds__(512, 1) attn_kernel(float* __restrict__ out) {
    extern __shared__ float sm[];

    const int bh = blockIdx.y;
    const int m0 = blockIdx.x * BM;
    const float* qg = g_q + (size_t)bh * NTOK * CDIM;
    const float* kg = g_k + (size_t)bh * NTOK * CDIM;
    const float* vg = g_v + (size_t)bh * NTOK * CDIM;

    const int tid = threadIdx.x;
    const int ty = tid >> 4;   // 0..31 : row group (4 rows)
    const int tx = tid & 15;   // 0..15 : col group (8 cols for S, 4 for PV)

    // ---- load Q tile, transposed + swizzled, pre-scaled by 1/8 ----
#pragma unroll
    for (int it = 0; it < 4; it++) {
        int fi = it * 512 + tid;          // 0..2047
        int r  = fi >> 4;                 // 0..127
        int c4 = (fi & 15) << 2;          // 0..60
        float4 t = *(const float4*)&qg[(size_t)(m0 + r) * 64 + c4];
        int sw = (c4 >> 2) & 7;
        int base = QT_OFF + c4 * TSTRIDE + ((((r >> 2) ^ sw)) << 2) + (r & 3);
        sm[base]               = t.x * 0.125f;
        sm[base + TSTRIDE]     = t.y * 0.125f;
        sm[base + 2 * TSTRIDE] = t.z * 0.125f;
        sm[base + 3 * TSTRIDE] = t.w * 0.125f;
    }

    u64 oacc[4][2];
    float mi[4], li[4];
#pragma unroll
    for (int i = 0; i < 4; i++) {
        oacc[i][0] = 0ull; oacc[i][1] = 0ull;
        mi[i] = -1e30f; li[i] = 0.f;
    }

    for (int kt = 0; kt < NTOK / BN; kt++) {
        const int k0 = kt * BN;
        __syncthreads();  // prev PV done reading Vs/Pt; prev S done reading Kt

        // ---- load K (transposed+swizzled) and V (row-major) tiles ----
#pragma unroll
        for (int it = 0; it < 4; it++) {
            int fi = it * 512 + tid;
            int r  = fi >> 4;
            int c4 = (fi & 15) << 2;
            float4 t = *(const float4*)&kg[(size_t)(k0 + r) * 64 + c4];
            int sw = (c4 >> 2) & 7;
            int base = KT_OFF + c4 * TSTRIDE + ((((r >> 2) ^ sw)) << 2) + (r & 3);
            sm[base]               = t.x;
            sm[base + TSTRIDE]     = t.y;
            sm[base + 2 * TSTRIDE] = t.z;
            sm[base + 3 * TSTRIDE] = t.w;

            float4 v = *(const float4*)&vg[(size_t)(k0 + r) * 64 + c4];
            *(float4*)&sm[VS_OFF + r * 68 + c4] = v;
        }
        __syncthreads();

        // ---- S = Q K^T : output rows ty*4+i, cols tx*8+(2p,2p+1) ----
        u64 acc[4][4];
#pragma unroll
        for (int i = 0; i < 4; i++)
#pragma unroll
            for (int p = 0; p < 4; p++) acc[i][p] = 0ull;

#pragma unroll 2
        for (int cb = 0; cb < 16; cb++) {
            const int sw = cb & 7;
            const float* qp  = &sm[QT_OFF + cb * (4 * TSTRIDE) + ((ty ^ sw) << 2)];
            const float* kp0 = &sm[KT_OFF + cb * (4 * TSTRIDE) + (((2 * tx) ^ sw) << 2)];
            const float* kp1 = &sm[KT_OFF + cb * (4 * TSTRIDE) + (((2 * tx + 1) ^ sw) << 2)];
#pragma unroll
            for (int cc = 0; cc < 4; cc++) {
                float4 qa = *(const float4*)(qp + cc * TSTRIDE);
                ull2 kb0 = *(const ull2*)(kp0 + cc * TSTRIDE);
                ull2 kb1 = *(const ull2*)(kp1 + cc * TSTRIDE);
                u64 qb;
                qb = pk2(qa.x, qa.x);
                acc[0][0] = f2fma(qb, kb0.x, acc[0][0]);
                acc[0][1] = f2fma(qb, kb0.y, acc[0][1]);
                acc[0][2] = f2fma(qb, kb1.x, acc[0][2]);
                acc[0][3] = f2fma(qb, kb1.y, acc[0][3]);
                qb = pk2(qa.y, qa.y);
                acc[1][0] = f2fma(qb, kb0.x, acc[1][0]);
                acc[1][1] = f2fma(qb, kb0.y, acc[1][1]);
                acc[1][2] = f2fma(qb, kb1.x, acc[1][2]);
                acc[1][3] = f2fma(qb, kb1.y, acc[1][3]);
                qb = pk2(qa.z, qa.z);
                acc[2][0] = f2fma(qb, kb0.x, acc[2][0]);
                acc[2][1] = f2fma(qb, kb0.y, acc[2][1]);
                acc[2][2] = f2fma(qb, kb1.x, acc[2][2]);
                acc[2][3] = f2fma(qb, kb1.y, acc[2][3]);
                qb = pk2(qa.w, qa.w);
                acc[3][0] = f2fma(qb, kb0.x, acc[3][0]);
                acc[3][1] = f2fma(qb, kb0.y, acc[3][1]);
                acc[3][2] = f2fma(qb, kb1.x, acc[3][2]);
                acc[3][3] = f2fma(qb, kb1.y, acc[3][3]);
            }
        }

        // unpack S
        float s[4][8];
#pragma unroll
        for (int i = 0; i < 4; i++)
#pragma unroll
            for (int p = 0; p < 4; p++)
                up2(acc[i][p], s[i][2 * p], s[i][2 * p + 1]);

        // ---- online softmax: row reduce over 16 tx lanes ----
        float alpha[4];
#pragma unroll
        for (int i = 0; i < 4; i++) {
            float m = s[i][0];
#pragma unroll
            for (int j = 1; j < 8; j++) m = fmaxf(m, s[i][j]);
#pragma unroll
            for (int off = 8; off > 0; off >>= 1)
                m = fmaxf(m, __shfl_xor_sync(0xffffffffu, m, off));
            float mn = fmaxf(mi[i], m);
            alpha[i] = __expf(mi[i] - mn);
            mi[i] = mn;
            float r = 0.f;
#pragma unroll
            for (int j = 0; j < 8; j++) { s[i][j] = __expf(s[i][j] - mn); r += s[i][j]; }
#pragma unroll
            for (int off = 8; off > 0; off >>= 1)
                r += __shfl_xor_sync(0xffffffffu, r, off);
            li[i] = li[i] * alpha[i] + r;
        }

        // rescale O
#pragma unroll
        for (int i = 0; i < 4; i++) {
            u64 ab = pk2(alpha[i], alpha[i]);
            oacc[i][0] = f2mul(oacc[i][0], ab);
            oacc[i][1] = f2mul(oacc[i][1], ab);
        }

        // publish P transposed+swizzled: Pt[col=tx*8+j][rows ty*4..+3]
#pragma unroll
        for (int j = 0; j < 8; j++) {
            int c = tx * 8 + j;
            int sw = (c >> 2) & 7;
            *(float4*)&sm[PT_OFF + c * TSTRIDE + ((ty ^ sw) << 2)] =
                make_float4(s[0][j], s[1][j], s[2][j], s[3][j]);
        }
        __syncthreads();

        // ---- O += P V : output rows ty*4+i, cols tx*4+(2p,2p+1) ----
#pragma unroll 2
        for (int kb = 0; kb < 32; kb++) {
            const int sw = kb & 7;
            const float* pp = &sm[PT_OFF + kb * (4 * TSTRIDE) + ((ty ^ sw) << 2)];
            const float* vp = &sm[VS_OFF + kb * (4 * 68) + (tx << 2)];
#pragma unroll
            for (int kc = 0; kc < 4; kc++) {
                float4 pa = *(const float4*)(pp + kc * TSTRIDE);
                ull2 vb = *(const ull2*)(vp + kc * 68);
                u64 pb;
                pb = pk2(pa.x, pa.x);
                oacc[0][0] = f2fma(pb, vb.x, oacc[0][0]);
                oacc[0][1] = f2fma(pb, vb.y, oacc[0][1]);
                pb = pk2(pa.y, pa.y);
                oacc[1][0] = f2fma(pb, vb.x, oacc[1][0]);
                oacc[1][1] = f2fma(pb, vb.y, oacc[1][1]);
                pb = pk2(pa.z, pa.z);
                oacc[2][0] = f2fma(pb, vb.x, oacc[2][0]);
                oacc[2][1] = f2fma(pb, vb.y, oacc[2][1]);
                pb = pk2(pa.w, pa.w);
                oacc[3][0] = f2fma(pb, vb.x, oacc[3][0]);
                oacc[3][1] = f2fma(pb, vb.y, oacc[3][1]);
            }
        }
    }

    // ---- epilogue: normalize + head-mixing shuffle ----
    // final[b, h', n, h*8 + j'] = attn_out[b, h, n, h'*8 + j']
    const int b = bh >> 3, h = bh & 7;
#pragma unroll
    for (int i = 0; i < 4; i++) {
        float inv = 1.0f / li[i];
        int n = m0 + ty * 4 + i;
        float ov[4];
        up2(oacc[i][0], ov[0], ov[1]);
        up2(oacc[i][1], ov[2], ov[3]);
#pragma unroll
        for (int j = 0; j < 4; j++) {
            int cc = tx * 4 + j;
            int hp = cc >> 3, jp = cc & 7;
            out[(((size_t)(b * 8 + hp) * NTOK + n) << 6) + h * 8 + jp] = ov[j] * inv;
        }
    }
}

// ---------------------------------------------------------------------------
extern "C" void kernel_launch(void* const* d_in, const int* in_sizes, int n_in,
                              void* d_out, int out_size) {
    const float* x = (const float*)d_in[0];      // [8,8,2048,64]
    const float* W = (const float*)d_in[1];      // [192,64]
    float* out = (float*)d_out;                  // [8,8,2048,64]

    cudaFuncSetAttribute(qkv_kernel,  cudaFuncAttributeMaxDynamicSharedMemorySize, 49152);
    cudaFuncSetAttribute(attn_kernel, cudaFuncAttributeMaxDynamicSharedMemorySize, SMEM_BYTES);

    qkv_kernel<<<(NBH * NTOK) / 256, 256, 49152>>>(x, W);
    attn_kernel<<<dim3(NTOK / BM, NBH), 256 * 2, SMEM_BYTES>>>(out);
}